// round 3
// baseline (speedup 1.0000x reference)
#include <cuda_runtime.h>

// Problem constants
#define D0   10
#define H0   200
#define W0_  176
#define C    64
#define HP   202          // H padded by 1 each side
#define WP   178          // W padded by 1 each side
#define SW   68           // smem row stride (floats), padded for bank-conflict-free reads
#define HW_OUT (H0 * W0_)

// Static scratch (zero-initialized at module load; halos are never written and stay 0)
__device__ float g_buf0[12 * HP * WP * C];  // padded dense input  (D pad 1 -> 12 planes)
__device__ float g_buf1[5  * HP * WP * C];  // conv1 out, H/W padded, D=5 unpadded
__device__ float g_buf2[5  * HP * WP * C];  // conv2 out at d=1..3, planes 0/4 stay zero (D pad)
__device__ int   g_owner[D0 * H0 * W0_];

// ---------------- scatter (duplicate resolution: last index wins) ----------------

__global__ void owner_init_k(int n) {
    int i = blockIdx.x * blockDim.x + threadIdx.x;
    if (i < n) g_owner[i] = -1;
}

__global__ void claim_k(const int* __restrict__ coors, int nvox) {
    int i = blockIdx.x * blockDim.x + threadIdx.x;
    if (i >= nvox) return;
    int d = coors[4*i+1], h = coors[4*i+2], w = coors[4*i+3];
    atomicMax(&g_owner[(d * H0 + h) * W0_ + w], i);
}

__global__ void scatter_k(const int* __restrict__ coors, const float* __restrict__ vf, int nvox) {
    int t = blockIdx.x * blockDim.x + threadIdx.x;
    int n = t >> 4, q = t & 15;
    if (n >= nvox) return;
    int d = coors[4*n+1], h = coors[4*n+2], w = coors[4*n+3];
    if (g_owner[(d * H0 + h) * W0_ + w] != n) return;
    float4 v = ((const float4*)vf)[n * 16 + q];
    float* dst = g_buf0 + (((size_t)(d + 1) * HP + (h + 1)) * WP + (w + 1)) * C;
    ((float4*)dst)[q] = v;
}

// ---------------- fused conv3x3x3 + scale + bias + relu ----------------
// Block: 352 threads = 8 ochan-groups x 44 w-groups; covers one full output row
// (h fixed, 176 w x 64 out-channels). Thread tile: 8 o x 4 w.
// in: padded layout [Dp][HP][WP][C], channels-last.
__global__ void __launch_bounds__(352, 2)
conv_k(const float* __restrict__ in, const float* __restrict__ wts,
       const float* __restrict__ scale, const float* __restrict__ bias,
       float* __restrict__ out, int stride_d, int final_mode, int d_shift)
{
    extern __shared__ float sm[];
    float* in_s = sm;               // [178][SW] input row, stride 68 floats
    float* ws   = sm + WP * SW;     // [64 i][3 kw][64 o] weight tap slice

    const int tid = threadIdx.x;
    const int ocg = tid & 7;        // 0..7
    const int wg  = tid >> 3;       // 0..43
    const int o0  = ocg * 8;
    const int w0  = wg * 4;
    const int h   = blockIdx.x;     // 0..199
    const int d   = blockIdx.y;     // output depth slice

    float acc[8][4];
#pragma unroll
    for (int r = 0; r < 8; r++)
#pragma unroll
        for (int k = 0; k < 4; k++) acc[r][k] = 0.f;

    const int rowC = WP * C;        // 11392
    const int dC   = HP * WP * C;   // 2301184

    for (int kd = 0; kd < 3; kd++) {
        const float* in_d = in + (size_t)(d * stride_d + kd) * dC;
        for (int kh = 0; kh < 3; kh++) {
            const float4* src4 = (const float4*)(in_d + (size_t)(h + kh) * rowC);
            __syncthreads();
            // stage input row: 178 w-positions x 16 float4 each
            for (int idx = tid; idx < WP * 16; idx += 352) {
                int w = idx >> 4, j = idx & 15;
                ((float4*)(in_s + w * SW))[j] = src4[idx];
            }
            // stage weight slice for this (kd,kh): layout [i][kw][o]
            const int tap3 = (kd * 3 + kh) * 3;
            for (int p = tid; p < 4096; p += 352) {
                int o = p >> 6, i = p & 63;
                const float* wsrc = wts + p * 27 + tap3;   // ((o*64+i)*27 + (kd*3+kh)*3)
                ws[(i * 3 + 0) * 64 + o] = wsrc[0];
                ws[(i * 3 + 1) * 64 + o] = wsrc[1];
                ws[(i * 3 + 2) * 64 + o] = wsrc[2];
            }
            __syncthreads();

            for (int i = 0; i < 64; i++) {
                float xv[6];
#pragma unroll
                for (int k = 0; k < 6; k++) xv[k] = in_s[(w0 + k) * SW + i];
#pragma unroll
                for (int kw = 0; kw < 3; kw++) {
                    const float4* wp4 = (const float4*)(ws + (i * 3 + kw) * 64 + o0);
                    float4 wa = wp4[0], wb = wp4[1];
                    float wv[8] = {wa.x, wa.y, wa.z, wa.w, wb.x, wb.y, wb.z, wb.w};
#pragma unroll
                    for (int r = 0; r < 8; r++)
#pragma unroll
                        for (int k = 0; k < 4; k++)
                            acc[r][k] = fmaf(wv[r], xv[k + kw], acc[r][k]);
                }
            }
        }
    }

    // epilogue: y = relu(conv * scale[o] + bias[o])
#pragma unroll
    for (int r = 0; r < 8; r++) {
        const int o = o0 + r;
        const float s = scale[o], b = bias[o];
        if (final_mode) {
            // out[(o*2 + d)][h][w]  (reshape (C,D,H,W) -> (C*D,H,W))
            float4 v4;
            float v0 = fmaf(acc[r][0], s, b); v4.x = v0 > 0.f ? v0 : 0.f;
            float v1 = fmaf(acc[r][1], s, b); v4.y = v1 > 0.f ? v1 : 0.f;
            float v2 = fmaf(acc[r][2], s, b); v4.z = v2 > 0.f ? v2 : 0.f;
            float v3 = fmaf(acc[r][3], s, b); v4.w = v3 > 0.f ? v3 : 0.f;
            *(float4*)(out + (size_t)(o * 2 + d) * HW_OUT + h * W0_ + w0) = v4;
        } else {
            float* op = out + ((size_t)(d + d_shift) * HP + (h + 1)) * (size_t)rowC
                            + (size_t)(w0 + 1) * C + o;
#pragma unroll
            for (int k = 0; k < 4; k++) {
                float v = fmaf(acc[r][k], s, b);
                op[k * C] = v > 0.f ? v : 0.f;
            }
        }
    }
}

// ---------------- launch ----------------

extern "C" void kernel_launch(void* const* d_in, const int* in_sizes, int n_in,
                              void* d_out, int out_size) {
    const float* vf    = (const float*)d_in[0];
    const int*   coors = (const int*)d_in[1];
    // batch_size may or may not be materialized as an input tensor
    const int base = (n_in >= 12) ? 3 : 2;
    const float* W1 = (const float*)d_in[base + 0];
    const float* s1 = (const float*)d_in[base + 1];
    const float* b1 = (const float*)d_in[base + 2];
    const float* W2 = (const float*)d_in[base + 3];
    const float* s2 = (const float*)d_in[base + 4];
    const float* b2 = (const float*)d_in[base + 5];
    const float* W3 = (const float*)d_in[base + 6];
    const float* s3 = (const float*)d_in[base + 7];
    const float* b3 = (const float*)d_in[base + 8];
    float* out = (float*)d_out;
    const int nvox = in_sizes[0] / C;

    float *buf0, *buf1, *buf2;
    cudaGetSymbolAddress((void**)&buf0, g_buf0);
    cudaGetSymbolAddress((void**)&buf1, g_buf1);
    cudaGetSymbolAddress((void**)&buf2, g_buf2);

    const size_t smem = (size_t)(WP * SW + 3 * 64 * 64) * sizeof(float);  // 97568 B
    cudaFuncSetAttribute(conv_k, cudaFuncAttributeMaxDynamicSharedMemorySize, (int)smem);

    // scatter with last-index-wins duplicate resolution
    owner_init_k<<<(D0 * H0 * W0_ + 255) / 256, 256>>>(D0 * H0 * W0_);
    claim_k<<<(nvox + 255) / 256, 256>>>(coors, nvox);
    scatter_k<<<(nvox * 16 + 255) / 256, 256>>>(coors, vf, nvox);

    // conv1: stride_d=2, pad(1,1,1): in buf0 (12 padded planes) -> buf1 d=0..4
    conv_k<<<dim3(200, 5), 352, smem>>>(buf0, W1, s1, b1, buf1, 2, 0, 0);
    // conv2: stride 1, pad(0,1,1): buf1 (D=5) -> buf2 planes 1..3 (0/4 stay zero = D pad)
    conv_k<<<dim3(200, 3), 352, smem>>>(buf1, W2, s2, b2, buf2, 1, 0, 1);
    // conv3: stride_d=2, pad(1,1,1): buf2 (5 padded planes) -> final output, reshaped
    conv_k<<<dim3(200, 2), 352, smem>>>(buf2, W3, s3, b3, out, 2, 1, 0);

    (void)out_size; (void)in_sizes; (void)n_in;
}

// round 4
// speedup vs baseline: 1.9482x; 1.9482x over previous
#include <cuda_runtime.h>
#include <cstdint>

// Problem constants
#define D0   10
#define H0   200
#define W0_  176
#define C    64
#define HP   202
#define WP   178
#define HW_OUT (H0 * W0_)

#define SWX  65                      // input smem row stride (floats): 8*65 % 32 = 8 -> conflict-free
#define IN_S_BYTES 46336             // WP*SWX*4 = 46280, padded to 128B multiple
#define WS_FLOATS (64 * 3 * 64)      // weight tap slice [i][kw][o]
#define SMEM_BYTES (IN_S_BYTES + WS_FLOATS * 4)   // 95488 B -> 2 blocks/SM

// Static scratch (zero-init at load; halos never written, stay 0)
__device__ float g_buf0[12 * HP * WP * C];
__device__ float g_buf1[5  * HP * WP * C];
__device__ float g_buf2[5  * HP * WP * C];
__device__ int   g_owner[D0 * H0 * W0_];
__device__ float g_wt1[9 * WS_FLOATS];
__device__ float g_wt2[9 * WS_FLOATS];
__device__ float g_wt3[9 * WS_FLOATS];

// ---------------- scatter (duplicate resolution: last index wins) ----------------

__global__ void owner_init_k(int n) {
    int i = blockIdx.x * blockDim.x + threadIdx.x;
    if (i < n) g_owner[i] = -1;
}

__global__ void claim_k(const int* __restrict__ coors, int nvox) {
    int i = blockIdx.x * blockDim.x + threadIdx.x;
    if (i >= nvox) return;
    int d = coors[4*i+1], h = coors[4*i+2], w = coors[4*i+3];
    atomicMax(&g_owner[(d * H0 + h) * W0_ + w], i);
}

__global__ void scatter_k(const int* __restrict__ coors, const float* __restrict__ vf, int nvox) {
    int t = blockIdx.x * blockDim.x + threadIdx.x;
    int n = t >> 4, q = t & 15;
    if (n >= nvox) return;
    int d = coors[4*n+1], h = coors[4*n+2], w = coors[4*n+3];
    if (g_owner[(d * H0 + h) * W0_ + w] != n) return;
    float4 v = ((const float4*)vf)[n * 16 + q];
    float* dst = g_buf0 + (((size_t)(d + 1) * HP + (h + 1)) * WP + (w + 1)) * C;
    ((float4*)dst)[q] = v;
}

// ---------------- weight pre-transform: W[o][i][kd][kh][kw] -> Wt[tap][i][kw][o] ----------------

__global__ void wtrans_k(const float* __restrict__ w, float* __restrict__ wt) {
    int idx = blockIdx.x * blockDim.x + threadIdx.x;
    if (idx >= 9 * WS_FLOATS) return;
    int o   = idx & 63;
    int kw  = (idx >> 6) % 3;
    int i   = (idx >> 6) / 3 % 64;
    int tap = idx / WS_FLOATS;
    wt[idx] = w[(o * 64 + i) * 27 + tap * 3 + kw];
}

// ---------------- fused conv3x3x3 + scale + bias + relu (FFMA2, 8o x 8w tile) ----------------
// Block: 176 threads = 8 ocg x 22 wgroups; one output row (h, d). Tile: 8 o x 8 w.
// Accumulators are packed f32x2 pairs along o (4 pairs x 8 w).
__global__ void __launch_bounds__(176, 2)
conv_k(const float* __restrict__ in, const float* __restrict__ wt,
       const float* __restrict__ scale, const float* __restrict__ bias,
       float* __restrict__ out, int stride_d, int final_mode, int d_shift)
{
    extern __shared__ float sm[];
    uint32_t sbase;
    asm("{ .reg .u64 t; cvta.to.shared.u64 t, %1; cvt.u32.u64 %0, t; }"
        : "=r"(sbase) : "l"(sm));
    const uint32_t ws_base = sbase + IN_S_BYTES;

    const int tid = threadIdx.x;
    const int ocg = tid & 7;        // 0..7
    const int wg  = tid >> 3;       // 0..21
    const int o0  = ocg * 8;
    const int w0  = wg * 8;
    const int h   = blockIdx.x;     // 0..199
    const int d   = blockIdx.y;     // output depth slice

    const int rowC = WP * C;        // 11392
    const int dC   = HP * WP * C;

    float sreg[8], breg[8];
#pragma unroll
    for (int r = 0; r < 8; r++) { sreg[r] = scale[o0 + r]; breg[r] = bias[o0 + r]; }

    unsigned long long acc[4][8];
#pragma unroll
    for (int p = 0; p < 4; p++)
#pragma unroll
        for (int k = 0; k < 8; k++) acc[p][k] = 0ULL;

    for (int kd = 0; kd < 3; kd++) {
        const float* in_d = in + (size_t)(d * stride_d + kd) * dC;
        for (int kh = 0; kh < 3; kh++) {
            __syncthreads();
            // stage input row [w][c] -> smem [w*SWX + c]; LDG coalesced, STS conflict-free
            const float* src = in_d + (size_t)(h + kh) * rowC;
            for (int idx = tid; idx < WP * C; idx += 176) {
                int w = idx >> 6, c = idx & 63;
                sm[w * SWX + c] = src[idx];
            }
            // stage weight tap slice: straight float4 memcpy (pre-transformed layout)
            {
                const float4* wsrc = (const float4*)(wt + (size_t)(kd * 3 + kh) * WS_FLOATS);
                float4* wdst = (float4*)(sm + IN_S_BYTES / 4);
                for (int idx = tid; idx < WS_FLOATS / 4; idx += 176) wdst[idx] = wsrc[idx];
            }
            __syncthreads();

            uint32_t xbase = sbase + (uint32_t)(w0 * SWX) * 4u;
            uint32_t wbase = ws_base + (uint32_t)o0 * 4u;
#pragma unroll 2
            for (int i = 0; i < 64; i++) {
                unsigned long long xp[10];
#pragma unroll
                for (int k = 0; k < 10; k++) {
                    unsigned xb;
                    asm("ld.shared.b32 %0, [%1];" : "=r"(xb) : "r"(xbase + (uint32_t)(k * SWX * 4)));
                    asm("mov.b64 %0, {%1, %1};" : "=l"(xp[k]) : "r"(xb));
                }
#pragma unroll
                for (int kw = 0; kw < 3; kw++) {
                    unsigned long long wq0, wq1, wq2, wq3;
                    asm("ld.shared.v2.b64 {%0, %1}, [%2];"
                        : "=l"(wq0), "=l"(wq1) : "r"(wbase + (uint32_t)(kw * 256)));
                    asm("ld.shared.v2.b64 {%0, %1}, [%2];"
                        : "=l"(wq2), "=l"(wq3) : "r"(wbase + (uint32_t)(kw * 256 + 16)));
#pragma unroll
                    for (int k = 0; k < 8; k++) {
                        asm("fma.rn.f32x2 %0, %1, %2, %0;" : "+l"(acc[0][k]) : "l"(wq0), "l"(xp[k + kw]));
                        asm("fma.rn.f32x2 %0, %1, %2, %0;" : "+l"(acc[1][k]) : "l"(wq1), "l"(xp[k + kw]));
                        asm("fma.rn.f32x2 %0, %1, %2, %0;" : "+l"(acc[2][k]) : "l"(wq2), "l"(xp[k + kw]));
                        asm("fma.rn.f32x2 %0, %1, %2, %0;" : "+l"(acc[3][k]) : "l"(wq3), "l"(xp[k + kw]));
                    }
                }
                xbase += 4;
                wbase += 768;
            }
        }
    }

    // epilogue: y = relu(conv * scale[o] + bias[o])
    // pair p holds channels (o0+2p) in lo 32 bits, (o0+2p+1) in hi 32 bits
    if (final_mode) {
#pragma unroll
        for (int r = 0; r < 8; r++) {
            float v[8];
#pragma unroll
            for (int k = 0; k < 8; k++) {
                unsigned long long a = acc[r >> 1][k];
                unsigned u = (r & 1) ? (unsigned)(a >> 32) : (unsigned)(a & 0xffffffffULL);
                float x = fmaf(__uint_as_float(u), sreg[r], breg[r]);
                v[k] = x > 0.f ? x : 0.f;
            }
            float* op = out + (size_t)((o0 + r) * 2 + d) * HW_OUT + h * W0_ + w0;
            *(float4*)op       = make_float4(v[0], v[1], v[2], v[3]);
            *(float4*)(op + 4) = make_float4(v[4], v[5], v[6], v[7]);
        }
    } else {
#pragma unroll
        for (int k = 0; k < 8; k++) {
            float v[8];
#pragma unroll
            for (int r = 0; r < 8; r++) {
                unsigned long long a = acc[r >> 1][k];
                unsigned u = (r & 1) ? (unsigned)(a >> 32) : (unsigned)(a & 0xffffffffULL);
                float x = fmaf(__uint_as_float(u), sreg[r], breg[r]);
                v[r] = x > 0.f ? x : 0.f;
            }
            float* op = out + ((size_t)(d + d_shift) * HP + (h + 1)) * (size_t)rowC
                            + (size_t)(w0 + 1 + k) * C + o0;
            *(float4*)op       = make_float4(v[0], v[1], v[2], v[3]);
            *(float4*)(op + 4) = make_float4(v[4], v[5], v[6], v[7]);
        }
    }
}

// ---------------- launch ----------------

extern "C" void kernel_launch(void* const* d_in, const int* in_sizes, int n_in,
                              void* d_out, int out_size) {
    const float* vf    = (const float*)d_in[0];
    const int*   coors = (const int*)d_in[1];
    const int base = (n_in >= 12) ? 3 : 2;
    const float* W1 = (const float*)d_in[base + 0];
    const float* s1 = (const float*)d_in[base + 1];
    const float* b1 = (const float*)d_in[base + 2];
    const float* W2 = (const float*)d_in[base + 3];
    const float* s2 = (const float*)d_in[base + 4];
    const float* b2 = (const float*)d_in[base + 5];
    const float* W3 = (const float*)d_in[base + 6];
    const float* s3 = (const float*)d_in[base + 7];
    const float* b3 = (const float*)d_in[base + 8];
    float* out = (float*)d_out;
    const int nvox = in_sizes[0] / C;

    float *buf0, *buf1, *buf2, *wt1, *wt2, *wt3;
    cudaGetSymbolAddress((void**)&buf0, g_buf0);
    cudaGetSymbolAddress((void**)&buf1, g_buf1);
    cudaGetSymbolAddress((void**)&buf2, g_buf2);
    cudaGetSymbolAddress((void**)&wt1, g_wt1);
    cudaGetSymbolAddress((void**)&wt2, g_wt2);
    cudaGetSymbolAddress((void**)&wt3, g_wt3);

    cudaFuncSetAttribute(conv_k, cudaFuncAttributeMaxDynamicSharedMemorySize, SMEM_BYTES);

    // scatter with last-index-wins duplicate resolution
    owner_init_k<<<(D0 * H0 * W0_ + 255) / 256, 256>>>(D0 * H0 * W0_);
    claim_k<<<(nvox + 255) / 256, 256>>>(coors, nvox);
    scatter_k<<<(nvox * 16 + 255) / 256, 256>>>(coors, vf, nvox);

    // weight pre-transform (coalesced staging layout)
    const int nw = 9 * WS_FLOATS;
    wtrans_k<<<(nw + 255) / 256, 256>>>(W1, wt1);
    wtrans_k<<<(nw + 255) / 256, 256>>>(W2, wt2);
    wtrans_k<<<(nw + 255) / 256, 256>>>(W3, wt3);

    // conv1: stride_d=2, pad(1,1,1): buf0 (12 padded planes) -> buf1 d=0..4
    conv_k<<<dim3(200, 5), 176, SMEM_BYTES>>>(buf0, wt1, s1, b1, buf1, 2, 0, 0);
    // conv2: stride 1, pad(0,1,1): buf1 (D=5) -> buf2 planes 1..3 (0/4 stay zero = D pad)
    conv_k<<<dim3(200, 3), 176, SMEM_BYTES>>>(buf1, wt2, s2, b2, buf2, 1, 0, 1);
    // conv3: stride_d=2, pad(1,1,1): buf2 (5 padded planes) -> final output, reshaped
    conv_k<<<dim3(200, 2), 176, SMEM_BYTES>>>(buf2, wt3, s3, b3, out, 2, 1, 0);

    (void)out_size; (void)in_sizes; (void)n_in;
}

// round 8
// speedup vs baseline: 2.6194x; 1.3445x over previous
#include <cuda_runtime.h>
#include <cstdint>

// Problem constants
#define D0   10
#define H0   200
#define W0_  176
#define C    64
#define HP   202
#define WP   178
#define HW_OUT (H0 * W0_)

#define SWX  68                      // input smem row stride (floats): 16B-aligned rows AND
                                     // conflict-free for wtile=11 (11*68 % 32 = 12 -> banks {0,12,24,4})
#define IN_S_BYTES 48512             // WP*SWX*4 = 48416, padded to 128B multiple
#define WS_FLOATS (64 * 3 * 64)      // weight tap slice [i][kw][o]
#define SMEM_BYTES (IN_S_BYTES + WS_FLOATS * 4)   // 97664 B -> 2 blocks/SM

// Static scratch (zero-init at load; halos never written, stay 0)
__device__ float g_buf0[12 * HP * WP * C];
__device__ float g_buf1[5  * HP * WP * C];
__device__ float g_buf2[5  * HP * WP * C];
__device__ int   g_owner[D0 * H0 * W0_];
__device__ float g_wt1[9 * WS_FLOATS];
__device__ float g_wt2[9 * WS_FLOATS];
__device__ float g_wt3[9 * WS_FLOATS];

// ---------------- scatter (duplicate resolution: last index wins) ----------------

__global__ void owner_init_k(int n) {
    int i = blockIdx.x * blockDim.x + threadIdx.x;
    if (i < n) g_owner[i] = -1;
}

__global__ void claim_k(const int* __restrict__ coors, int nvox) {
    int i = blockIdx.x * blockDim.x + threadIdx.x;
    if (i >= nvox) return;
    int d = coors[4*i+1], h = coors[4*i+2], w = coors[4*i+3];
    atomicMax(&g_owner[(d * H0 + h) * W0_ + w], i);
}

__global__ void scatter_k(const int* __restrict__ coors, const float* __restrict__ vf, int nvox) {
    int t = blockIdx.x * blockDim.x + threadIdx.x;
    int n = t >> 4, q = t & 15;
    if (n >= nvox) return;
    int d = coors[4*n+1], h = coors[4*n+2], w = coors[4*n+3];
    if (g_owner[(d * H0 + h) * W0_ + w] != n) return;
    float4 v = ((const float4*)vf)[n * 16 + q];
    float* dst = g_buf0 + (((size_t)(d + 1) * HP + (h + 1)) * WP + (w + 1)) * C;
    ((float4*)dst)[q] = v;
}

// ---------------- weight pre-transform: W[o][i][kd][kh][kw] -> Wt[tap][i][kw][o] ----------------

__global__ void wtrans_k(const float* __restrict__ w, float* __restrict__ wt) {
    int idx = blockIdx.x * blockDim.x + threadIdx.x;
    if (idx >= 9 * WS_FLOATS) return;
    int o   = idx & 63;
    int kw  = (idx >> 6) % 3;
    int i   = (idx >> 6) / 3 % 64;
    int tap = idx / WS_FLOATS;
    wt[idx] = w[(o * 64 + i) * 27 + tap * 3 + kw];
}

// ---------------- fused conv3x3x3 + scale + bias + relu (FFMA2, 8o x 11w tile) ----------------
// Block: 128 threads = 4 FULL warps = 8 ocg x 16 wg; one output row (h, d).
// Thread tile: 8 o (4 f32x2 pairs) x 11 w -> 44 packed accumulators.
__global__ void __launch_bounds__(128, 2)
conv_k(const float* __restrict__ in, const float* __restrict__ wt,
       const float* __restrict__ scale, const float* __restrict__ bias,
       float* __restrict__ out, int stride_d, int final_mode, int d_shift)
{
    extern __shared__ float sm[];
    uint32_t sbase;
    asm("{ .reg .u64 t; cvta.to.shared.u64 t, %1; cvt.u32.u64 %0, t; }"
        : "=r"(sbase) : "l"(sm));
    const uint32_t ws_base = sbase + IN_S_BYTES;

    const int tid = threadIdx.x;
    const int ocg = tid & 7;        // 0..7
    const int wg  = tid >> 3;       // 0..15
    const int o0  = ocg * 8;
    const int w0  = wg * 11;
    const int h   = blockIdx.x;     // 0..199
    const int d   = blockIdx.y;     // output depth slice

    const int rowC = WP * C;        // 11392
    const int dC   = HP * WP * C;

    unsigned long long acc[4][11];
#pragma unroll
    for (int p = 0; p < 4; p++)
#pragma unroll
        for (int k = 0; k < 11; k++) acc[p][k] = 0ULL;

    for (int kd = 0; kd < 3; kd++) {
        const float* in_d = in + (size_t)(d * stride_d + kd) * dC;
        for (int kh = 0; kh < 3; kh++) {
            __syncthreads();
            // stage input row via cp.async: 178 w x 16 float4 (dst stride 17 float4)
            {
                const float4* src4 = (const float4*)(in_d + (size_t)(h + kh) * rowC);
                for (int idx = tid; idx < WP * 16; idx += 128) {
                    int w = idx >> 4, j = idx & 15;
                    uint32_t dst = sbase + (uint32_t)(w * 17 + j) * 16u;
                    asm volatile("cp.async.ca.shared.global [%0], [%1], 16;"
                                 :: "r"(dst), "l"(src4 + idx));
                }
            }
            // stage weight tap slice (contiguous float4 copy)
            {
                const float4* wsrc = (const float4*)(wt + (size_t)(kd * 3 + kh) * WS_FLOATS);
                for (int idx = tid; idx < WS_FLOATS / 4; idx += 128) {
                    uint32_t dst = ws_base + (uint32_t)idx * 16u;
                    asm volatile("cp.async.ca.shared.global [%0], [%1], 16;"
                                 :: "r"(dst), "l"(wsrc + idx));
                }
            }
            asm volatile("cp.async.commit_group;");
            asm volatile("cp.async.wait_group 0;");
            __syncthreads();

            uint32_t xbase = sbase + (uint32_t)(w0 * SWX) * 4u;
            uint32_t wbase = ws_base + (uint32_t)o0 * 4u;
#pragma unroll 2
            for (int i = 0; i < 64; i++) {
                unsigned long long xp[13];
#pragma unroll
                for (int k = 0; k < 13; k++) {
                    unsigned xb;
                    asm("ld.shared.b32 %0, [%1];" : "=r"(xb) : "r"(xbase + (uint32_t)(k * SWX * 4)));
                    asm("mov.b64 %0, {%1, %1};" : "=l"(xp[k]) : "r"(xb));
                }
#pragma unroll
                for (int kw = 0; kw < 3; kw++) {
                    unsigned long long wq0, wq1, wq2, wq3;
                    asm("ld.shared.v2.b64 {%0, %1}, [%2];"
                        : "=l"(wq0), "=l"(wq1) : "r"(wbase + (uint32_t)(kw * 256)));
                    asm("ld.shared.v2.b64 {%0, %1}, [%2];"
                        : "=l"(wq2), "=l"(wq3) : "r"(wbase + (uint32_t)(kw * 256 + 16)));
#pragma unroll
                    for (int k = 0; k < 11; k++) {
                        asm("fma.rn.f32x2 %0, %1, %2, %0;" : "+l"(acc[0][k]) : "l"(wq0), "l"(xp[k + kw]));
                        asm("fma.rn.f32x2 %0, %1, %2, %0;" : "+l"(acc[1][k]) : "l"(wq1), "l"(xp[k + kw]));
                        asm("fma.rn.f32x2 %0, %1, %2, %0;" : "+l"(acc[2][k]) : "l"(wq2), "l"(xp[k + kw]));
                        asm("fma.rn.f32x2 %0, %1, %2, %0;" : "+l"(acc[3][k]) : "l"(wq3), "l"(xp[k + kw]));
                    }
                }
                xbase += 4;
                wbase += 768;
            }
        }
    }

    // epilogue: y = relu(conv * scale[o] + bias[o])
    float sreg[8], breg[8];
#pragma unroll
    for (int r = 0; r < 8; r++) { sreg[r] = scale[o0 + r]; breg[r] = bias[o0 + r]; }

    if (final_mode) {
#pragma unroll
        for (int r = 0; r < 8; r++) {
            float* op = out + (size_t)((o0 + r) * 2 + d) * HW_OUT + h * W0_ + w0;
#pragma unroll
            for (int k = 0; k < 11; k++) {
                unsigned long long a = acc[r >> 1][k];
                unsigned u = (r & 1) ? (unsigned)(a >> 32) : (unsigned)(a & 0xffffffffULL);
                float x = fmaf(__uint_as_float(u), sreg[r], breg[r]);
                op[k] = x > 0.f ? x : 0.f;
            }
        }
    } else {
#pragma unroll
        for (int k = 0; k < 11; k++) {
            float v[8];
#pragma unroll
            for (int r = 0; r < 8; r++) {
                unsigned long long a = acc[r >> 1][k];
                unsigned u = (r & 1) ? (unsigned)(a >> 32) : (unsigned)(a & 0xffffffffULL);
                float x = fmaf(__uint_as_float(u), sreg[r], breg[r]);
                v[r] = x > 0.f ? x : 0.f;
            }
            float* op = out + ((size_t)(d + d_shift) * HP + (h + 1)) * (size_t)rowC
                            + (size_t)(w0 + 1 + k) * C + o0;
            *(float4*)op       = make_float4(v[0], v[1], v[2], v[3]);
            *(float4*)(op + 4) = make_float4(v[4], v[5], v[6], v[7]);
        }
    }
}

// ---------------- launch ----------------

extern "C" void kernel_launch(void* const* d_in, const int* in_sizes, int n_in,
                              void* d_out, int out_size) {
    const float* vf    = (const float*)d_in[0];
    const int*   coors = (const int*)d_in[1];
    const int base = (n_in >= 12) ? 3 : 2;
    const float* W1 = (const float*)d_in[base + 0];
    const float* s1 = (const float*)d_in[base + 1];
    const float* b1 = (const float*)d_in[base + 2];
    const float* W2 = (const float*)d_in[base + 3];
    const float* s2 = (const float*)d_in[base + 4];
    const float* b2 = (const float*)d_in[base + 5];
    const float* W3 = (const float*)d_in[base + 6];
    const float* s3 = (const float*)d_in[base + 7];
    const float* b3 = (const float*)d_in[base + 8];
    float* out = (float*)d_out;
    const int nvox = in_sizes[0] / C;

    float *buf0, *buf1, *buf2, *wt1, *wt2, *wt3;
    cudaGetSymbolAddress((void**)&buf0, g_buf0);
    cudaGetSymbolAddress((void**)&buf1, g_buf1);
    cudaGetSymbolAddress((void**)&buf2, g_buf2);
    cudaGetSymbolAddress((void**)&wt1, g_wt1);
    cudaGetSymbolAddress((void**)&wt2, g_wt2);
    cudaGetSymbolAddress((void**)&wt3, g_wt3);

    cudaFuncSetAttribute(conv_k, cudaFuncAttributeMaxDynamicSharedMemorySize, SMEM_BYTES);

    const int nw = 9 * WS_FLOATS;

    // Launch order chosen so conv1 is the 6th launch (ncu -s 5 -c 1 captures it).
    owner_init_k<<<(D0 * H0 * W0_ + 255) / 256, 256>>>(D0 * H0 * W0_);          // 1
    claim_k<<<(nvox + 255) / 256, 256>>>(coors, nvox);                          // 2
    scatter_k<<<(nvox * 16 + 255) / 256, 256>>>(coors, vf, nvox);               // 3
    wtrans_k<<<(nw + 255) / 256, 256>>>(W1, wt1);                               // 4
    wtrans_k<<<(nw + 255) / 256, 256>>>(W2, wt2);                               // 5
    // conv1: stride_d=2, pad(1,1,1): buf0 (12 padded planes) -> buf1 d=0..4
    conv_k<<<dim3(200, 5), 128, SMEM_BYTES>>>(buf0, wt1, s1, b1, buf1, 2, 0, 0); // 6
    wtrans_k<<<(nw + 255) / 256, 256>>>(W3, wt3);                               // 7
    // conv2: stride 1, pad(0,1,1): buf1 (D=5) -> buf2 planes 1..3
    conv_k<<<dim3(200, 3), 128, SMEM_BYTES>>>(buf1, wt2, s2, b2, buf2, 1, 0, 1); // 8
    // conv3: stride_d=2, pad(1,1,1): buf2 (5 padded planes) -> final output, reshaped
    conv_k<<<dim3(200, 2), 128, SMEM_BYTES>>>(buf2, wt3, s3, b3, out, 2, 1, 0);  // 9

    (void)out_size; (void)in_sizes; (void)n_in;
}

// round 10
// speedup vs baseline: 2.6206x; 1.0004x over previous
#include <cuda_runtime.h>
#include <cstdint>

// Problem constants
#define D0   10
#define H0   200
#define W0_  176
#define C    64
#define HP   202
#define WP   178
#define HW_OUT (H0 * W0_)

#define SWX  68                      // input smem row stride (floats): 16B-aligned rows AND
                                     // conflict-free for wtile=11 (11*68 % 32 = 12 -> banks {0,12,24,4})
#define IN_S_BYTES 48512             // WP*SWX*4 = 48416, padded to 128B multiple
#define WS_FLOATS (64 * 3 * 64)      // weight tap slice [i][kw][o]
#define SMEM_BYTES (IN_S_BYTES + WS_FLOATS * 4)   // 97664 B -> 2 blocks/SM

// Static scratch (zero-init at load; halos never written, stay 0)
__device__ float g_buf0[12 * HP * WP * C];
__device__ float g_buf1[5  * HP * WP * C];
__device__ float g_buf2[5  * HP * WP * C];
__device__ int   g_owner[D0 * H0 * W0_];
__device__ float g_wt1[9 * WS_FLOATS];
__device__ float g_wt2[9 * WS_FLOATS];
__device__ float g_wt3[9 * WS_FLOATS];

// ---------------- scatter (duplicate resolution: last index wins) ----------------

__global__ void owner_init_k(int n) {
    int i = blockIdx.x * blockDim.x + threadIdx.x;
    if (i < n) g_owner[i] = -1;
}

__global__ void claim_k(const int* __restrict__ coors, int nvox) {
    int i = blockIdx.x * blockDim.x + threadIdx.x;
    if (i >= nvox) return;
    int d = coors[4*i+1], h = coors[4*i+2], w = coors[4*i+3];
    atomicMax(&g_owner[(d * H0 + h) * W0_ + w], i);
}

__global__ void scatter_k(const int* __restrict__ coors, const float* __restrict__ vf, int nvox) {
    int t = blockIdx.x * blockDim.x + threadIdx.x;
    int n = t >> 4, q = t & 15;
    if (n >= nvox) return;
    int d = coors[4*n+1], h = coors[4*n+2], w = coors[4*n+3];
    if (g_owner[(d * H0 + h) * W0_ + w] != n) return;
    float4 v = ((const float4*)vf)[n * 16 + q];
    float* dst = g_buf0 + (((size_t)(d + 1) * HP + (h + 1)) * WP + (w + 1)) * C;
    ((float4*)dst)[q] = v;
}

// ---------------- weight pre-transform: W[o][i][kd][kh][kw] -> Wt[tap][i][kw][o] ----------------

__global__ void wtrans_k(const float* __restrict__ w, float* __restrict__ wt) {
    int idx = blockIdx.x * blockDim.x + threadIdx.x;
    if (idx >= 9 * WS_FLOATS) return;
    int o   = idx & 63;
    int kw  = (idx >> 6) % 3;
    int i   = (idx >> 6) / 3 % 64;
    int tap = idx / WS_FLOATS;
    wt[idx] = w[(o * 64 + i) * 27 + tap * 3 + kw];
}

// ---------------- fused conv3x3x3 + scale + bias + relu (FFMA2, 8o x 11w tile) ----------------
// Block: 128 threads = 4 FULL warps = 8 ocg x 16 wg; one output row (h, d).
// Thread tile: 8 o (4 f32x2 pairs) x 11 w -> 44 packed accumulators.
__global__ void __launch_bounds__(128, 2)
conv_k(const float* __restrict__ in, const float* __restrict__ wt,
       const float* __restrict__ scale, const float* __restrict__ bias,
       float* __restrict__ out, int stride_d, int final_mode, int d_shift)
{
    extern __shared__ float sm[];
    uint32_t sbase;
    asm("{ .reg .u64 t; cvta.to.shared.u64 t, %1; cvt.u32.u64 %0, t; }"
        : "=r"(sbase) : "l"(sm));
    const uint32_t ws_base = sbase + IN_S_BYTES;

    const int tid = threadIdx.x;
    const int ocg = tid & 7;        // 0..7
    const int wg  = tid >> 3;       // 0..15
    const int o0  = ocg * 8;
    const int w0  = wg * 11;
    const int h   = blockIdx.x;     // 0..199
    const int d   = blockIdx.y;     // output depth slice

    const int rowC = WP * C;        // 11392
    const int dC   = HP * WP * C;

    unsigned long long acc[4][11];
#pragma unroll
    for (int p = 0; p < 4; p++)
#pragma unroll
        for (int k = 0; k < 11; k++) acc[p][k] = 0ULL;

    for (int kd = 0; kd < 3; kd++) {
        const float* in_d = in + (size_t)(d * stride_d + kd) * dC;
        for (int kh = 0; kh < 3; kh++) {
            __syncthreads();
            // stage input row via cp.async: 178 w x 16 float4 (dst stride 17 float4)
            {
                const float4* src4 = (const float4*)(in_d + (size_t)(h + kh) * rowC);
                for (int idx = tid; idx < WP * 16; idx += 128) {
                    int w = idx >> 4, j = idx & 15;
                    uint32_t dst = sbase + (uint32_t)(w * 17 + j) * 16u;
                    asm volatile("cp.async.ca.shared.global [%0], [%1], 16;"
                                 :: "r"(dst), "l"(src4 + idx));
                }
            }
            // stage weight tap slice (contiguous float4 copy)
            {
                const float4* wsrc = (const float4*)(wt + (size_t)(kd * 3 + kh) * WS_FLOATS);
                for (int idx = tid; idx < WS_FLOATS / 4; idx += 128) {
                    uint32_t dst = ws_base + (uint32_t)idx * 16u;
                    asm volatile("cp.async.ca.shared.global [%0], [%1], 16;"
                                 :: "r"(dst), "l"(wsrc + idx));
                }
            }
            asm volatile("cp.async.commit_group;");
            asm volatile("cp.async.wait_group 0;");
            __syncthreads();

            uint32_t xbase = sbase + (uint32_t)(w0 * SWX) * 4u;
            uint32_t wbase = ws_base + (uint32_t)o0 * 4u;
#pragma unroll 2
            for (int i = 0; i < 64; i++) {
                unsigned long long xp[13];
#pragma unroll
                for (int k = 0; k < 13; k++) {
                    unsigned xb;
                    asm("ld.shared.b32 %0, [%1];" : "=r"(xb) : "r"(xbase + (uint32_t)(k * SWX * 4)));
                    asm("mov.b64 %0, {%1, %1};" : "=l"(xp[k]) : "r"(xb));
                }
#pragma unroll
                for (int kw = 0; kw < 3; kw++) {
                    unsigned long long wq0, wq1, wq2, wq3;
                    asm("ld.shared.v2.b64 {%0, %1}, [%2];"
                        : "=l"(wq0), "=l"(wq1) : "r"(wbase + (uint32_t)(kw * 256)));
                    asm("ld.shared.v2.b64 {%0, %1}, [%2];"
                        : "=l"(wq2), "=l"(wq3) : "r"(wbase + (uint32_t)(kw * 256 + 16)));
#pragma unroll
                    for (int k = 0; k < 11; k++) {
                        asm("fma.rn.f32x2 %0, %1, %2, %0;" : "+l"(acc[0][k]) : "l"(wq0), "l"(xp[k + kw]));
                        asm("fma.rn.f32x2 %0, %1, %2, %0;" : "+l"(acc[1][k]) : "l"(wq1), "l"(xp[k + kw]));
                        asm("fma.rn.f32x2 %0, %1, %2, %0;" : "+l"(acc[2][k]) : "l"(wq2), "l"(xp[k + kw]));
                        asm("fma.rn.f32x2 %0, %1, %2, %0;" : "+l"(acc[3][k]) : "l"(wq3), "l"(xp[k + kw]));
                    }
                }
                xbase += 4;
                wbase += 768;
            }
        }
    }

    // epilogue: y = relu(conv * scale[o] + bias[o])
    float sreg[8], breg[8];
#pragma unroll
    for (int r = 0; r < 8; r++) { sreg[r] = scale[o0 + r]; breg[r] = bias[o0 + r]; }

    if (final_mode) {
#pragma unroll
        for (int r = 0; r < 8; r++) {
            float* op = out + (size_t)((o0 + r) * 2 + d) * HW_OUT + h * W0_ + w0;
#pragma unroll
            for (int k = 0; k < 11; k++) {
                unsigned long long a = acc[r >> 1][k];
                unsigned u = (r & 1) ? (unsigned)(a >> 32) : (unsigned)(a & 0xffffffffULL);
                float x = fmaf(__uint_as_float(u), sreg[r], breg[r]);
                op[k] = x > 0.f ? x : 0.f;
            }
        }
    } else {
#pragma unroll
        for (int k = 0; k < 11; k++) {
            float v[8];
#pragma unroll
            for (int r = 0; r < 8; r++) {
                unsigned long long a = acc[r >> 1][k];
                unsigned u = (r & 1) ? (unsigned)(a >> 32) : (unsigned)(a & 0xffffffffULL);
                float x = fmaf(__uint_as_float(u), sreg[r], breg[r]);
                v[r] = x > 0.f ? x : 0.f;
            }
            float* op = out + ((size_t)(d + d_shift) * HP + (h + 1)) * (size_t)rowC
                            + (size_t)(w0 + 1 + k) * C + o0;
            *(float4*)op       = make_float4(v[0], v[1], v[2], v[3]);
            *(float4*)(op + 4) = make_float4(v[4], v[5], v[6], v[7]);
        }
    }
}

// ---------------- launch ----------------

extern "C" void kernel_launch(void* const* d_in, const int* in_sizes, int n_in,
                              void* d_out, int out_size) {
    const float* vf    = (const float*)d_in[0];
    const int*   coors = (const int*)d_in[1];
    const int base = (n_in >= 12) ? 3 : 2;
    const float* W1 = (const float*)d_in[base + 0];
    const float* s1 = (const float*)d_in[base + 1];
    const float* b1 = (const float*)d_in[base + 2];
    const float* W2 = (const float*)d_in[base + 3];
    const float* s2 = (const float*)d_in[base + 4];
    const float* b2 = (const float*)d_in[base + 5];
    const float* W3 = (const float*)d_in[base + 6];
    const float* s3 = (const float*)d_in[base + 7];
    const float* b3 = (const float*)d_in[base + 8];
    float* out = (float*)d_out;
    const int nvox = in_sizes[0] / C;

    float *buf0, *buf1, *buf2, *wt1, *wt2, *wt3;
    cudaGetSymbolAddress((void**)&buf0, g_buf0);
    cudaGetSymbolAddress((void**)&buf1, g_buf1);
    cudaGetSymbolAddress((void**)&buf2, g_buf2);
    cudaGetSymbolAddress((void**)&wt1, g_wt1);
    cudaGetSymbolAddress((void**)&wt2, g_wt2);
    cudaGetSymbolAddress((void**)&wt3, g_wt3);

    cudaFuncSetAttribute(conv_k, cudaFuncAttributeMaxDynamicSharedMemorySize, SMEM_BYTES);

    const int nw = 9 * WS_FLOATS;

    // Launch order chosen so conv1 is the 6th launch (ncu -s 5 -c 1 captures it).
    owner_init_k<<<(D0 * H0 * W0_ + 255) / 256, 256>>>(D0 * H0 * W0_);          // 1
    claim_k<<<(nvox + 255) / 256, 256>>>(coors, nvox);                          // 2
    scatter_k<<<(nvox * 16 + 255) / 256, 256>>>(coors, vf, nvox);               // 3
    wtrans_k<<<(nw + 255) / 256, 256>>>(W1, wt1);                               // 4
    wtrans_k<<<(nw + 255) / 256, 256>>>(W2, wt2);                               // 5
    // conv1: stride_d=2, pad(1,1,1): buf0 (12 padded planes) -> buf1 d=0..4
    conv_k<<<dim3(200, 5), 128, SMEM_BYTES>>>(buf0, wt1, s1, b1, buf1, 2, 0, 0); // 6
    wtrans_k<<<(nw + 255) / 256, 256>>>(W3, wt3);                               // 7
    // conv2: stride 1, pad(0,1,1): buf1 (D=5) -> buf2 planes 1..3
    conv_k<<<dim3(200, 3), 128, SMEM_BYTES>>>(buf1, wt2, s2, b2, buf2, 1, 0, 1); // 8
    // conv3: stride_d=2, pad(1,1,1): buf2 (5 padded planes) -> final output, reshaped
    conv_k<<<dim3(200, 2), 128, SMEM_BYTES>>>(buf2, wt3, s3, b3, out, 2, 1, 0);  // 9

    (void)out_size; (void)in_sizes; (void)n_in;
}